// round 10
// baseline (speedup 1.0000x reference)
#include <cuda_runtime.h>
#include <cuda_bf16.h>
#include <cstdint>
#include <math.h>

#define NSPK 512
#define UU   32
#define DD   512
#define NU   (NSPK*UU)
#define EPS  1e-8f

// ---------------- device scratch (no cudaMalloc allowed) ----------------
__device__ __nv_bfloat16 g_Ebf[(size_t)NU * DD];   // normalized embeddings, bf16 (16 MB)
__device__ __nv_bfloat16 g_Cbf[NSPK * DD];         // normalized centroids, bf16 (0.5 MB)
__device__ float         g_part[256];              // per-GEMM-block partial sums
__device__ int           g_ctr;                    // zero-init completion counter

// ---------------- PTX helpers (sm_80-class only: no tcgen05 on this target) ----
static __device__ __forceinline__ uint32_t smem_u32(const void* p) {
    uint32_t a;
    asm("{ .reg .u64 t; cvta.to.shared.u64 t, %1; cvt.u32.u64 %0, t; }" : "=r"(a) : "l"(p));
    return a;
}
static __device__ __forceinline__ void ldsm_x4(uint32_t& r0, uint32_t& r1,
                                               uint32_t& r2, uint32_t& r3, uint32_t addr) {
    asm volatile("ldmatrix.sync.aligned.m8n8.x4.shared.b16 {%0,%1,%2,%3}, [%4];"
                 : "=r"(r0), "=r"(r1), "=r"(r2), "=r"(r3) : "r"(addr));
}
static __device__ __forceinline__ void mma16816(float& d0, float& d1, float& d2, float& d3,
                                                uint32_t a0, uint32_t a1, uint32_t a2, uint32_t a3,
                                                uint32_t b0, uint32_t b1) {
    asm volatile(
        "mma.sync.aligned.m16n8k16.row.col.f32.bf16.bf16.f32 "
        "{%0,%1,%2,%3}, {%4,%5,%6,%7}, {%8,%9}, {%0,%1,%2,%3};"
        : "+f"(d0), "+f"(d1), "+f"(d2), "+f"(d3)
        : "r"(a0), "r"(a1), "r"(a2), "r"(a3), "r"(b0), "r"(b1));
}
static __device__ __forceinline__ void cpa16(uint32_t dst, const void* gsrc) {
    unsigned long long g = (unsigned long long)__cvta_generic_to_global(gsrc);
    asm volatile("cp.async.cg.shared.global [%0], [%1], 16;" :: "r"(dst), "l"(g));
}

// ---------------------------------------------------------------------------
// Kernel P: per-speaker pass (centroid+norm fused, packed bf16 writes)
// grid = 512, 256 threads, 64KB dynamic smem
// ---------------------------------------------------------------------------
__global__ void __launch_bounds__(256, 1) prep_kernel(const float* __restrict__ emb) {
    extern __shared__ float s[];
    __shared__ float red[9];
    const int n = blockIdx.x, tid = threadIdx.x;
    const int w = tid >> 5, lane = tid & 31;

    const float4* src = reinterpret_cast<const float4*>(emb) + (size_t)n * 4096;
    float4* s4 = reinterpret_cast<float4*>(s);
    #pragma unroll
    for (int i = 0; i < 16; i++) s4[tid + i * 256] = src[tid + i * 256];
    __syncthreads();

    float c0 = 0.f, c1 = 0.f;
    #pragma unroll
    for (int u = 0; u < UU; u++) {
        c0 += s[u * DD + tid];
        c1 += s[u * DD + tid + 256];
    }
    c0 *= (1.0f / UU); c1 *= (1.0f / UU);
    float sq = fmaf(c0, c0, c1 * c1);
    #pragma unroll
    for (int o = 16; o > 0; o >>= 1) sq += __shfl_xor_sync(0xffffffffu, sq, o);
    if (lane == 0) red[w] = sq;
    __syncthreads();
    if (tid == 0) {
        float t = 0.f;
        #pragma unroll
        for (int i = 0; i < 8; i++) t += red[i];
        red[8] = 1.0f / fmaxf(sqrtf(t), EPS);
    }
    __syncthreads();
    const float invc = red[8];
    g_Cbf[n * DD + tid]       = __float2bfloat16(c0 * invc);
    g_Cbf[n * DD + tid + 256] = __float2bfloat16(c1 * invc);

    for (int u = w; u < UU; u += 8) {
        const float4* rowp = reinterpret_cast<const float4*>(s + u * DD);
        float4 v[4]; float ss = 0.f;
        #pragma unroll
        for (int j = 0; j < 4; j++) {
            v[j] = rowp[lane + j * 32];
            ss = fmaf(v[j].x, v[j].x, ss);
            ss = fmaf(v[j].y, v[j].y, ss);
            ss = fmaf(v[j].z, v[j].z, ss);
            ss = fmaf(v[j].w, v[j].w, ss);
        }
        #pragma unroll
        for (int o = 16; o > 0; o >>= 1) ss += __shfl_xor_sync(0xffffffffu, ss, o);
        const float inv = 1.0f / fmaxf(sqrtf(ss), EPS);
        uint2* dst = reinterpret_cast<uint2*>(g_Ebf + ((size_t)n * UU + u) * DD);
        #pragma unroll
        for (int j = 0; j < 4; j++) {
            __nv_bfloat162 lo = __floats2bfloat162_rn(v[j].x * inv, v[j].y * inv);
            __nv_bfloat162 hi = __floats2bfloat162_rn(v[j].z * inv, v[j].w * inv);
            uint2 pk;
            pk.x = *reinterpret_cast<uint32_t*>(&lo);
            pk.y = *reinterpret_cast<uint32_t*>(&hi);
            dst[lane + j * 32] = pk;
        }
    }
}

// ---------------------------------------------------------------------------
// Kernel G: HMMA GEMM + fused online log-softmax + fused final reduction.
// Block = 64 rows; A resident (64KB); B = 8 chunks of 64 speakers, dbl-buffered.
// grid = 256, 256 threads = 8 warps: warp grid 2(M) x 4(N), warp tile 32x16.
// ---------------------------------------------------------------------------
#define SM_A   0
#define SM_B(s) (65536 + (s) * 65536)
#define SM_TOT 196608
#define SWZ_OFF(r, cb) ((uint32_t)((r) * 1024 + ((((cb)) ^ ((r) & 7)) << 4)))

static __device__ __forceinline__ void load_B_chunk(uint32_t sb, int c, int tid) {
    const uint32_t buf = sb + SM_B(c & 1);
    const __nv_bfloat16* src = g_Cbf + (size_t)c * 64 * DD;
    #pragma unroll
    for (int it = 0; it < 16; it++) {
        const int u = tid + it * 256;
        const int r = u >> 6, cb = u & 63;
        cpa16(buf + SWZ_OFF(r, cb), src + (size_t)r * DD + cb * 8);
    }
    asm volatile("cp.async.commit_group;" ::: "memory");
}

__global__ void __launch_bounds__(256, 1)
gemm_loss_kernel(const float* __restrict__ wp, const float* __restrict__ bp,
                 float* __restrict__ out) {
    extern __shared__ char smem[];
    __shared__ int lastflag;
    const uint32_t sb = smem_u32(smem);
    const int tid = threadIdx.x, wid = tid >> 5, lane = tid & 31;
    const int bi = blockIdx.x;
    const int wm = wid & 1;        // row half (32 rows)
    const int wn = wid >> 1;       // 16-col stripe within 64-speaker chunk (0..3)
    const int l7 = lane & 7;

    // ---- prologue: A + B0 (group 0), then B1 (group 1) ----
    {
        const __nv_bfloat16* As = g_Ebf + (size_t)bi * 64 * DD;
        #pragma unroll
        for (int it = 0; it < 16; it++) {
            const int u = tid + it * 256;
            const int r = u >> 6, cb = u & 63;
            cpa16(sb + SM_A + SWZ_OFF(r, cb), As + (size_t)r * DD + cb * 8);
        }
        const __nv_bfloat16* Bs = g_Cbf;
        #pragma unroll
        for (int it = 0; it < 16; it++) {
            const int u = tid + it * 256;
            const int r = u >> 6, cb = u & 63;
            cpa16(sb + SM_B(0) + SWZ_OFF(r, cb), Bs + (size_t)r * DD + cb * 8);
        }
        asm volatile("cp.async.commit_group;" ::: "memory");
        load_B_chunk(sb, 1, tid);
    }

    // per-thread ldmatrix addressing
    const uint32_t aoff0 = sb + SM_A + (uint32_t)(wm * 32 + (lane & 15)) * 1024;
    const uint32_t aoff1 = aoff0 + 16 * 1024;
    const int cbA = lane >> 4;              // A k-half select
    const int khB = (lane >> 3) & 1;        // B k-half select (x4 form)
    // B x4: lanes 0-7 -> (nt0, kh0), 8-15 -> (nt0, kh1), 16-23 -> (nt1, kh0), 24-31 -> (nt1, kh1)
    const uint32_t brow = (uint32_t)((wn * 16 + (lane >> 4) * 8 + l7) * 1024);

    // diagonal bookkeeping (warp-uniform speaker index)
    const int diag = bi * 2 + wm;
    const int dchunk = diag >> 6;           // 64-speaker chunk
    const int cc = diag & 63;               // col within chunk
    const int dwn = cc >> 4;                // 16-col stripe
    const int dj = cc & 15;                 // col within warp tile
    const int dnt = dj >> 3, down = (dj & 7) >> 1, de = dj & 1;

    float om[4], os[4], od[4];
    #pragma unroll
    for (int i = 0; i < 4; i++) { om[i] = -INFINITY; os[i] = 0.f; od[i] = 0.f; }

    const float Wv = wp[0], Bv = bp[0];

    for (int c = 0; c < 8; c++) {
        if (c < 7) asm volatile("cp.async.wait_group 1;" ::: "memory");
        else       asm volatile("cp.async.wait_group 0;" ::: "memory");
        __syncthreads();

        const uint32_t Bbuf = sb + SM_B(c & 1);
        float acc[2][2][4];
        #pragma unroll
        for (int mt = 0; mt < 2; mt++)
            #pragma unroll
            for (int nt = 0; nt < 2; nt++)
                #pragma unroll
                for (int e = 0; e < 4; e++) acc[mt][nt][e] = 0.f;

        #pragma unroll 4
        for (int kk = 0; kk < 32; kk++) {
            const int cb = kk * 2;
            uint32_t a[2][4];
            ldsm_x4(a[0][0], a[0][1], a[0][2], a[0][3],
                    aoff0 + ((uint32_t)((cb + cbA) ^ l7) << 4));
            ldsm_x4(a[1][0], a[1][1], a[1][2], a[1][3],
                    aoff1 + ((uint32_t)((cb + cbA) ^ l7) << 4));
            uint32_t b[2][2];
            ldsm_x4(b[0][0], b[0][1], b[1][0], b[1][1],
                    Bbuf + brow + ((uint32_t)((cb + khB) ^ l7) << 4));
            #pragma unroll
            for (int mt = 0; mt < 2; mt++)
                #pragma unroll
                for (int nt = 0; nt < 2; nt++)
                    mma16816(acc[mt][nt][0], acc[mt][nt][1], acc[mt][nt][2], acc[mt][nt][3],
                             a[mt][0], a[mt][1], a[mt][2], a[mt][3], b[nt][0], b[nt][1]);
        }

        // ---- online log-softmax update over this chunk's 4 cols per row ----
        const bool dhit = (c == dchunk) && (wn == dwn) && ((lane & 3) == down);
        #pragma unroll
        for (int mt = 0; mt < 2; mt++) {
            #pragma unroll
            for (int h = 0; h < 2; h++) {
                const int si = mt * 2 + h;
                float v[4], vmax;
                #pragma unroll
                for (int nt = 0; nt < 2; nt++) {
                    v[nt * 2 + 0] = fmaf(Wv, acc[mt][nt][h * 2 + 0], Bv);
                    v[nt * 2 + 1] = fmaf(Wv, acc[mt][nt][h * 2 + 1], Bv);
                }
                vmax = fmaxf(fmaxf(v[0], v[1]), fmaxf(v[2], v[3]));
                const float nm = fmaxf(om[si], vmax);
                float add = 0.f;
                #pragma unroll
                for (int j = 0; j < 4; j++) add += __expf(v[j] - nm);
                os[si] = os[si] * __expf(om[si] - nm) + add;
                om[si] = nm;
                if (dhit) od[si] += v[dnt * 2 + de];
            }
        }

        __syncthreads();
        if (c + 2 < 8) load_B_chunk(sb, c + 2, tid);
    }

    // ---- combine (m,s,d) across the 4 lanes of each row quad ----
    float fm[4], fs[4], fd[4];
    #pragma unroll
    for (int si = 0; si < 4; si++) {
        float m = om[si], s = os[si], d = od[si];
        #pragma unroll
        for (int off = 1; off <= 2; off <<= 1) {
            const float mo = __shfl_xor_sync(0xffffffffu, m, off);
            const float so = __shfl_xor_sync(0xffffffffu, s, off);
            const float dd = __shfl_xor_sync(0xffffffffu, d, off);
            const float nm = fmaxf(m, mo);
            s = s * __expf(m - nm) + so * __expf(mo - nm);
            m = nm;
            d += dd;
        }
        fm[si] = m; fs[si] = s; fd[si] = d;
    }

    // ---- merge the 4 column-stripe warps per row-half via smem ----
    float* sm_m = (float*)smem;            // [8][32]  (A region dead now)
    float* sm_s = sm_m + 256;              // [8][32]
    float* sm_d = sm_s + 256;              // [8][32]
    __syncthreads();
    if ((lane & 3) == 0) {
        #pragma unroll
        for (int si = 0; si < 4; si++) {
            const int r = (si >> 1) * 16 + (si & 1) * 8 + (lane >> 2);
            sm_m[wid * 32 + r] = fm[si];
            sm_s[wid * 32 + r] = fs[si];
            sm_d[wid * 32 + r] = fd[si];
        }
    }
    __syncthreads();

    if (wid < 2) {   // warp q merges rows of half wm=q from wids q, q+2, q+4, q+6
        float m = -INFINITY, s = 0.f, d = 0.f;
        #pragma unroll
        for (int p = 0; p < 4; p++) {
            const int src = wid + p * 2;
            const float mi = sm_m[src * 32 + lane];
            const float si_ = sm_s[src * 32 + lane];
            const float di = sm_d[src * 32 + lane];
            const float nm = fmaxf(m, mi);
            s = s * __expf(m - nm) + si_ * __expf(mi - nm);
            m = nm;
            d += di;
        }
        float local = d - m - __logf(s);
        #pragma unroll
        for (int o = 16; o > 0; o >>= 1)
            local += __shfl_xor_sync(0xffffffffu, local, o);
        if (lane == 0) sm_m[wid] = local;
    }
    __syncthreads();

    // ---- fused finalize: last block deterministically reduces g_part ----
    if (tid == 0) {
        g_part[bi] = sm_m[0] + sm_m[1];
        __threadfence();
        lastflag = (atomicAdd(&g_ctr, 1) == 255);
    }
    __syncthreads();
    if (lastflag) {
        float t = (tid < 256) ? g_part[tid] : 0.f;
        #pragma unroll
        for (int o = 16; o > 0; o >>= 1)
            t += __shfl_xor_sync(0xffffffffu, t, o);
        if (lane == 0) sm_s[wid] = t;
        __syncthreads();
        if (tid == 0) {
            float tt = 0.f;
            #pragma unroll
            for (int i = 0; i < 8; i++) tt += sm_s[i];
            out[0] = -tt * (1.0f / (float)NU);
            g_ctr = 0;   // reset for next graph replay
        }
    }
}

extern "C" void kernel_launch(void* const* d_in, const int* in_sizes, int n_in,
                              void* d_out, int out_size) {
    const float* emb = (const float*)d_in[0];
    const float* w = (const float*)d_in[1];
    const float* b = (const float*)d_in[2];
    float* out = (float*)d_out;

    cudaFuncSetAttribute(prep_kernel, cudaFuncAttributeMaxDynamicSharedMemorySize, 65536);
    cudaFuncSetAttribute(gemm_loss_kernel, cudaFuncAttributeMaxDynamicSharedMemorySize, SM_TOT);

    prep_kernel<<<NSPK, 256, 65536>>>(emb);
    gemm_loss_kernel<<<256, 256, SM_TOT>>>(w, b, out);
}

// round 11
// speedup vs baseline: 1.0959x; 1.0959x over previous
#include <cuda_runtime.h>
#include <cuda_bf16.h>
#include <cstdint>
#include <math.h>

#define NSPK 512
#define UU   32
#define DD   512
#define NU   (NSPK*UU)
#define EPS  1e-8f

// ---------------- device scratch (no cudaMalloc allowed) ----------------
__device__ __nv_bfloat16 g_Ebf[(size_t)NU * DD];   // normalized embeddings, bf16 (16 MB)
__device__ __nv_bfloat16 g_Cbf[NSPK * DD];         // normalized centroids, bf16 (0.5 MB)
__device__ float         g_part[256];              // per-GEMM-block partial sums
__device__ int           g_ctr;                    // zero-init completion counter

// ---------------- PTX helpers (sm_80-class only: no tcgen05 on this target) ----
static __device__ __forceinline__ uint32_t smem_u32(const void* p) {
    uint32_t a;
    asm("{ .reg .u64 t; cvta.to.shared.u64 t, %1; cvt.u32.u64 %0, t; }" : "=r"(a) : "l"(p));
    return a;
}
static __device__ __forceinline__ void ldsm_x4(uint32_t& r0, uint32_t& r1,
                                               uint32_t& r2, uint32_t& r3, uint32_t addr) {
    asm volatile("ldmatrix.sync.aligned.m8n8.x4.shared.b16 {%0,%1,%2,%3}, [%4];"
                 : "=r"(r0), "=r"(r1), "=r"(r2), "=r"(r3) : "r"(addr));
}
static __device__ __forceinline__ void ldsm_x2(uint32_t& r0, uint32_t& r1, uint32_t addr) {
    asm volatile("ldmatrix.sync.aligned.m8n8.x2.shared.b16 {%0,%1}, [%2];"
                 : "=r"(r0), "=r"(r1) : "r"(addr));
}
static __device__ __forceinline__ void mma16816(float& d0, float& d1, float& d2, float& d3,
                                                uint32_t a0, uint32_t a1, uint32_t a2, uint32_t a3,
                                                uint32_t b0, uint32_t b1) {
    asm volatile(
        "mma.sync.aligned.m16n8k16.row.col.f32.bf16.bf16.f32 "
        "{%0,%1,%2,%3}, {%4,%5,%6,%7}, {%8,%9}, {%0,%1,%2,%3};"
        : "+f"(d0), "+f"(d1), "+f"(d2), "+f"(d3)
        : "r"(a0), "r"(a1), "r"(a2), "r"(a3), "r"(b0), "r"(b1));
}
static __device__ __forceinline__ void cpa16(uint32_t dst, const void* gsrc) {
    unsigned long long g = (unsigned long long)__cvta_generic_to_global(gsrc);
    asm volatile("cp.async.cg.shared.global [%0], [%1], 16;" :: "r"(dst), "l"(g));
}

// ---------------------------------------------------------------------------
// Kernel P: per-speaker pass (centroid+norm fused, packed bf16 writes)
// grid = 512, 256 threads, 64KB dynamic smem
// ---------------------------------------------------------------------------
__global__ void __launch_bounds__(256, 1) prep_kernel(const float* __restrict__ emb) {
    extern __shared__ float s[];
    __shared__ float red[9];
    const int n = blockIdx.x, tid = threadIdx.x;
    const int w = tid >> 5, lane = tid & 31;

    const float4* src = reinterpret_cast<const float4*>(emb) + (size_t)n * 4096;
    float4* s4 = reinterpret_cast<float4*>(s);
    #pragma unroll
    for (int i = 0; i < 16; i++) s4[tid + i * 256] = src[tid + i * 256];
    __syncthreads();

    float c0 = 0.f, c1 = 0.f;
    #pragma unroll
    for (int u = 0; u < UU; u++) {
        c0 += s[u * DD + tid];
        c1 += s[u * DD + tid + 256];
    }
    c0 *= (1.0f / UU); c1 *= (1.0f / UU);
    float sq = fmaf(c0, c0, c1 * c1);
    #pragma unroll
    for (int o = 16; o > 0; o >>= 1) sq += __shfl_xor_sync(0xffffffffu, sq, o);
    if (lane == 0) red[w] = sq;
    __syncthreads();
    if (tid == 0) {
        float t = 0.f;
        #pragma unroll
        for (int i = 0; i < 8; i++) t += red[i];
        red[8] = 1.0f / fmaxf(sqrtf(t), EPS);
    }
    __syncthreads();
    const float invc = red[8];
    g_Cbf[n * DD + tid]       = __float2bfloat16(c0 * invc);
    g_Cbf[n * DD + tid + 256] = __float2bfloat16(c1 * invc);

    for (int u = w; u < UU; u += 8) {
        const float4* rowp = reinterpret_cast<const float4*>(s + u * DD);
        float4 v[4]; float ss = 0.f;
        #pragma unroll
        for (int j = 0; j < 4; j++) {
            v[j] = rowp[lane + j * 32];
            ss = fmaf(v[j].x, v[j].x, ss);
            ss = fmaf(v[j].y, v[j].y, ss);
            ss = fmaf(v[j].z, v[j].z, ss);
            ss = fmaf(v[j].w, v[j].w, ss);
        }
        #pragma unroll
        for (int o = 16; o > 0; o >>= 1) ss += __shfl_xor_sync(0xffffffffu, ss, o);
        const float inv = 1.0f / fmaxf(sqrtf(ss), EPS);
        uint2* dst = reinterpret_cast<uint2*>(g_Ebf + ((size_t)n * UU + u) * DD);
        #pragma unroll
        for (int j = 0; j < 4; j++) {
            __nv_bfloat162 lo = __floats2bfloat162_rn(v[j].x * inv, v[j].y * inv);
            __nv_bfloat162 hi = __floats2bfloat162_rn(v[j].z * inv, v[j].w * inv);
            uint2 pk;
            pk.x = *reinterpret_cast<uint32_t*>(&lo);
            pk.y = *reinterpret_cast<uint32_t*>(&hi);
            dst[lane + j * 32] = pk;
        }
    }
}

// ---------------------------------------------------------------------------
// Kernel G: HMMA GEMM (exact R5 structure) + shift-free softmax + fused finalize.
// Block = 64 rows; A resident (64KB); B = 8 chunks of 64 speakers, dbl-buffered.
// grid = 256, 128 threads (4 warps, 2x2 of 32x32 warp tiles).
// Logits are bounded (|w|+|b| ~ 15), so exp() needs no max shift: the softmax
// reduces to plain sums of exp(v), merged additively across lanes/warps.
// ---------------------------------------------------------------------------
#define SM_A   0
#define SM_B(s) (65536 + (s) * 65536)
#define SM_TOT 196608
#define SWZ_OFF(r, cb) ((uint32_t)((r) * 1024 + ((((cb)) ^ ((r) & 7)) << 4)))

static __device__ __forceinline__ void load_B_chunk(uint32_t sb, int c, int tid) {
    const uint32_t buf = sb + SM_B(c & 1);
    const __nv_bfloat16* src = g_Cbf + (size_t)c * 64 * DD;
    #pragma unroll
    for (int it = 0; it < 32; it++) {
        const int u = tid + it * 128;
        const int r = u >> 6, cb = u & 63;
        cpa16(buf + SWZ_OFF(r, cb), src + (size_t)r * DD + cb * 8);
    }
    asm volatile("cp.async.commit_group;" ::: "memory");
}

__global__ void __launch_bounds__(128, 1)
gemm_loss_kernel(const float* __restrict__ wp, const float* __restrict__ bp,
                 float* __restrict__ out) {
    extern __shared__ char smem[];
    __shared__ int lastflag;
    const uint32_t sb = smem_u32(smem);
    const int tid = threadIdx.x, wid = tid >> 5, lane = tid & 31;
    const int bi = blockIdx.x;
    const int wm = wid & 1;        // row half
    const int wn = wid >> 1;       // col half within 64-speaker chunk
    const int l7 = lane & 7;

    // ---- prologue: A + B0 (group 0), then B1 (group 1) ----
    {
        const __nv_bfloat16* As = g_Ebf + (size_t)bi * 64 * DD;
        #pragma unroll
        for (int it = 0; it < 32; it++) {
            const int u = tid + it * 128;
            const int r = u >> 6, cb = u & 63;
            cpa16(sb + SM_A + SWZ_OFF(r, cb), As + (size_t)r * DD + cb * 8);
        }
        const __nv_bfloat16* Bs = g_Cbf;
        #pragma unroll
        for (int it = 0; it < 32; it++) {
            const int u = tid + it * 128;
            const int r = u >> 6, cb = u & 63;
            cpa16(sb + SM_B(0) + SWZ_OFF(r, cb), Bs + (size_t)r * DD + cb * 8);
        }
        asm volatile("cp.async.commit_group;" ::: "memory");
        load_B_chunk(sb, 1, tid);
    }

    // per-thread ldmatrix addressing (R5 form)
    const uint32_t aoff0 = sb + SM_A + (uint32_t)(wm * 32 + (lane & 15)) * 1024;
    const uint32_t aoff1 = aoff0 + 16 * 1024;
    const int cbA = lane >> 4;          // A k-half select
    const int cbB = (lane >> 3) & 1;    // B k-half select (x2 form)
    uint32_t brow[4];
    #pragma unroll
    for (int nt = 0; nt < 4; nt++)
        brow[nt] = (uint32_t)((wn * 32 + nt * 8 + l7) * 1024);

    // diagonal bookkeeping (warp-uniform speaker index)
    const int diag = bi * 2 + wm;
    const int dchunk = diag >> 6;
    const int dwn = (diag >> 5) & 1;
    const int dj = diag & 31;
    const int dnt = dj >> 3, down = (dj & 7) >> 1, de = dj & 1;

    // shift-free softmax state: sum of exp, diag value, per row-set
    float os[4], od[4];
    #pragma unroll
    for (int i = 0; i < 4; i++) { os[i] = 0.f; od[i] = 0.f; }

    const float Wv = wp[0], Bv = bp[0];

    for (int c = 0; c < 8; c++) {
        if (c < 7) asm volatile("cp.async.wait_group 1;" ::: "memory");
        else       asm volatile("cp.async.wait_group 0;" ::: "memory");
        __syncthreads();

        const uint32_t Bbuf = sb + SM_B(c & 1);
        float acc[2][4][4];
        #pragma unroll
        for (int mt = 0; mt < 2; mt++)
            #pragma unroll
            for (int nt = 0; nt < 4; nt++)
                #pragma unroll
                for (int e = 0; e < 4; e++) acc[mt][nt][e] = 0.f;

        #pragma unroll 8
        for (int kk = 0; kk < 32; kk++) {
            const int cb = kk * 2;
            uint32_t a[2][4];
            ldsm_x4(a[0][0], a[0][1], a[0][2], a[0][3],
                    aoff0 + ((uint32_t)((cb + cbA) ^ l7) << 4));
            ldsm_x4(a[1][0], a[1][1], a[1][2], a[1][3],
                    aoff1 + ((uint32_t)((cb + cbA) ^ l7) << 4));
            uint32_t b[4][2];
            #pragma unroll
            for (int nt = 0; nt < 4; nt++)
                ldsm_x2(b[nt][0], b[nt][1],
                        Bbuf + brow[nt] + ((uint32_t)((cb + cbB) ^ l7) << 4));
            #pragma unroll
            for (int mt = 0; mt < 2; mt++)
                #pragma unroll
                for (int nt = 0; nt < 4; nt++)
                    mma16816(acc[mt][nt][0], acc[mt][nt][1], acc[mt][nt][2], acc[mt][nt][3],
                             a[mt][0], a[mt][1], a[mt][2], a[mt][3], b[nt][0], b[nt][1]);
        }

        // ---- shift-free softmax accumulation (8 cols per row-set) ----
        const bool dhit = (c == dchunk) && (wn == dwn) && ((lane & 3) == down);
        #pragma unroll
        for (int mt = 0; mt < 2; mt++) {
            #pragma unroll
            for (int h = 0; h < 2; h++) {
                const int si = mt * 2 + h;
                float add = 0.f;
                #pragma unroll
                for (int nt = 0; nt < 4; nt++) {
                    const float v0 = fmaf(Wv, acc[mt][nt][h * 2 + 0], Bv);
                    const float v1 = fmaf(Wv, acc[mt][nt][h * 2 + 1], Bv);
                    add += __expf(v0) + __expf(v1);
                    if (dhit && nt == dnt) od[si] += (de ? v1 : v0);
                }
                os[si] += add;
            }
        }

        __syncthreads();
        if (c + 2 < 8) load_B_chunk(sb, c + 2, tid);
    }

    // ---- combine sums across the 4 lanes of each row quad ----
    #pragma unroll
    for (int si = 0; si < 4; si++) {
        #pragma unroll
        for (int off = 1; off <= 2; off <<= 1) {
            os[si] += __shfl_xor_sync(0xffffffffu, os[si], off);
            od[si] += __shfl_xor_sync(0xffffffffu, od[si], off);
        }
    }

    // ---- merge the two column-half warps (0<->2, 1<->3) via smem ----
    float* sm_s = (float*)smem;          // [4][32]  (A region dead now)
    float* sm_d = sm_s + 128;            // [4][32]
    float* sm_r = sm_d + 128;            // partials
    __syncthreads();
    if ((lane & 3) == 0) {
        #pragma unroll
        for (int si = 0; si < 4; si++) {
            const int r = (si >> 1) * 16 + (si & 1) * 8 + (lane >> 2);
            sm_s[wid * 32 + r] = os[si];
            sm_d[wid * 32 + r] = od[si];
        }
    }
    __syncthreads();

    if (wid < 2) {
        const float s = sm_s[wid * 32 + lane] + sm_s[(wid + 2) * 32 + lane];
        const float d = sm_d[wid * 32 + lane] + sm_d[(wid + 2) * 32 + lane];
        float local = d - __logf(s);
        #pragma unroll
        for (int o = 16; o > 0; o >>= 1)
            local += __shfl_xor_sync(0xffffffffu, local, o);
        if (lane == 0) sm_r[wid] = local;
    }
    __syncthreads();

    // ---- fused finalize: last block deterministically reduces g_part ----
    if (tid == 0) {
        g_part[bi] = sm_r[0] + sm_r[1];
        __threadfence();
        lastflag = (atomicAdd(&g_ctr, 1) == 255);
    }
    __syncthreads();
    if (lastflag) {
        float t = g_part[tid] + g_part[tid + 128];
        #pragma unroll
        for (int o = 16; o > 0; o >>= 1)
            t += __shfl_xor_sync(0xffffffffu, t, o);
        if (lane == 0) sm_r[4 + wid] = t;
        __syncthreads();
        if (tid == 0) {
            out[0] = -(sm_r[4] + sm_r[5] + sm_r[6] + sm_r[7]) * (1.0f / (float)NU);
            g_ctr = 0;   // reset for next graph replay
        }
    }
}

extern "C" void kernel_launch(void* const* d_in, const int* in_sizes, int n_in,
                              void* d_out, int out_size) {
    const float* emb = (const float*)d_in[0];
    const float* w = (const float*)d_in[1];
    const float* b = (const float*)d_in[2];
    float* out = (float*)d_out;

    cudaFuncSetAttribute(prep_kernel, cudaFuncAttributeMaxDynamicSharedMemorySize, 65536);
    cudaFuncSetAttribute(gemm_loss_kernel, cudaFuncAttributeMaxDynamicSharedMemorySize, SM_TOT);

    prep_kernel<<<NSPK, 256, 65536>>>(emb);
    gemm_loss_kernel<<<256, 128, SM_TOT>>>(w, b, out);
}

// round 13
// speedup vs baseline: 1.1849x; 1.0812x over previous
#include <cuda_runtime.h>
#include <cuda_bf16.h>
#include <cstdint>
#include <math.h>

#define NSPK 512
#define UU   32
#define DD   512
#define NU   (NSPK*UU)
#define EPS  1e-8f

// ---------------- device scratch (no cudaMalloc allowed) ----------------
__device__ __nv_bfloat16 g_Ebf[(size_t)NU * DD];   // normalized embeddings, bf16 (16 MB)
__device__ __nv_bfloat16 g_Cbf[NSPK * DD];         // normalized centroids, bf16 (0.5 MB)
__device__ float         g_part[128];              // per-GEMM-block partial sums
__device__ int           g_ctr;                    // zero-init completion counter

// ---------------- PTX helpers ----------------
static __device__ __forceinline__ uint32_t smem_u32(const void* p) {
    uint32_t a;
    asm("{ .reg .u64 t; cvta.to.shared.u64 t, %1; cvt.u32.u64 %0, t; }" : "=r"(a) : "l"(p));
    return a;
}
static __device__ __forceinline__ void ldsm_x4(uint32_t& r0, uint32_t& r1,
                                               uint32_t& r2, uint32_t& r3, uint32_t addr) {
    asm volatile("ldmatrix.sync.aligned.m8n8.x4.shared.b16 {%0,%1,%2,%3}, [%4];"
                 : "=r"(r0), "=r"(r1), "=r"(r2), "=r"(r3) : "r"(addr));
}
static __device__ __forceinline__ void mma16816(float& d0, float& d1, float& d2, float& d3,
                                                uint32_t a0, uint32_t a1, uint32_t a2, uint32_t a3,
                                                uint32_t b0, uint32_t b1) {
    asm volatile(
        "mma.sync.aligned.m16n8k16.row.col.f32.bf16.bf16.f32 "
        "{%0,%1,%2,%3}, {%4,%5,%6,%7}, {%8,%9}, {%0,%1,%2,%3};"
        : "+f"(d0), "+f"(d1), "+f"(d2), "+f"(d3)
        : "r"(a0), "r"(a1), "r"(a2), "r"(a3), "r"(b0), "r"(b1));
}
static __device__ __forceinline__ void cpa16(uint32_t dst, const void* gsrc) {
    unsigned long long g = (unsigned long long)__cvta_generic_to_global(gsrc);
    asm volatile("cp.async.cg.shared.global [%0], [%1], 16;" :: "r"(dst), "l"(g));
}

// ---------------------------------------------------------------------------
// Kernel P: per-speaker pass (centroid+norm fused, packed bf16 writes)
// grid = 512, 256 threads, 64KB dynamic smem
// ---------------------------------------------------------------------------
__global__ void __launch_bounds__(256, 1) prep_kernel(const float* __restrict__ emb) {
    extern __shared__ float s[];
    __shared__ float red[9];
    const int n = blockIdx.x, tid = threadIdx.x;
    const int w = tid >> 5, lane = tid & 31;

    const float4* src = reinterpret_cast<const float4*>(emb) + (size_t)n * 4096;
    float4* s4 = reinterpret_cast<float4*>(s);
    #pragma unroll
    for (int i = 0; i < 16; i++) s4[tid + i * 256] = src[tid + i * 256];
    __syncthreads();

    float c0 = 0.f, c1 = 0.f;
    #pragma unroll
    for (int u = 0; u < UU; u++) {
        c0 += s[u * DD + tid];
        c1 += s[u * DD + tid + 256];
    }
    c0 *= (1.0f / UU); c1 *= (1.0f / UU);
    float sq = fmaf(c0, c0, c1 * c1);
    #pragma unroll
    for (int o = 16; o > 0; o >>= 1) sq += __shfl_xor_sync(0xffffffffu, sq, o);
    if (lane == 0) red[w] = sq;
    __syncthreads();
    if (tid == 0) {
        float t = 0.f;
        #pragma unroll
        for (int i = 0; i < 8; i++) t += red[i];
        red[8] = 1.0f / fmaxf(sqrtf(t), EPS);
    }
    __syncthreads();
    const float invc = red[8];
    g_Cbf[n * DD + tid]       = __float2bfloat16(c0 * invc);
    g_Cbf[n * DD + tid + 256] = __float2bfloat16(c1 * invc);

    for (int u = w; u < UU; u += 8) {
        const float4* rowp = reinterpret_cast<const float4*>(s + u * DD);
        float4 v[4]; float ss = 0.f;
        #pragma unroll
        for (int j = 0; j < 4; j++) {
            v[j] = rowp[lane + j * 32];
            ss = fmaf(v[j].x, v[j].x, ss);
            ss = fmaf(v[j].y, v[j].y, ss);
            ss = fmaf(v[j].z, v[j].z, ss);
            ss = fmaf(v[j].w, v[j].w, ss);
        }
        #pragma unroll
        for (int o = 16; o > 0; o >>= 1) ss += __shfl_xor_sync(0xffffffffu, ss, o);
        const float inv = 1.0f / fmaxf(sqrtf(ss), EPS);
        uint2* dst = reinterpret_cast<uint2*>(g_Ebf + ((size_t)n * UU + u) * DD);
        #pragma unroll
        for (int j = 0; j < 4; j++) {
            __nv_bfloat162 lo = __floats2bfloat162_rn(v[j].x * inv, v[j].y * inv);
            __nv_bfloat162 hi = __floats2bfloat162_rn(v[j].z * inv, v[j].w * inv);
            uint2 pk;
            pk.x = *reinterpret_cast<uint32_t*>(&lo);
            pk.y = *reinterpret_cast<uint32_t*>(&hi);
            dst[lane + j * 32] = pk;
        }
    }
}

// ---------------------------------------------------------------------------
// Kernel G: HMMA GEMM, single wave. Block = 128 rows (A resident, 128KB);
// B = 16 chunks of 32 speakers, double-buffered (2x32KB).
// grid = 128, 256 threads = 8 warps: warp grid 4(M) x 2(N), warp tile 32x16.
// Shift-free softmax (logits bounded by |w|+|b|), fused final reduction.
// ---------------------------------------------------------------------------
#define SM_A   0
#define SM_B(s) (131072 + (s) * 32768)
#define SM_TOT 196608
#define SWZ_OFF(r, cb) ((uint32_t)((r) * 1024 + ((((cb)) ^ ((r) & 7)) << 4)))

static __device__ __forceinline__ void load_B_chunk(uint32_t sb, int c, int tid) {
    const uint32_t buf = sb + SM_B(c & 1);
    const __nv_bfloat16* src = g_Cbf + (size_t)c * 32 * DD;
    #pragma unroll
    for (int it = 0; it < 8; it++) {
        const int u = tid + it * 256;
        const int r = u >> 6, cb = u & 63;
        cpa16(buf + SWZ_OFF(r, cb), src + (size_t)r * DD + cb * 8);
    }
    asm volatile("cp.async.commit_group;" ::: "memory");
}

__global__ void __launch_bounds__(256, 1)
gemm_loss_kernel(const float* __restrict__ wp, const float* __restrict__ bp,
                 float* __restrict__ out) {
    extern __shared__ char smem[];
    __shared__ int lastflag;
    const uint32_t sb = smem_u32(smem);
    const int tid = threadIdx.x, wid = tid >> 5, lane = tid & 31;
    const int bi = blockIdx.x;
    const int wm = wid & 3;        // row quarter (32 rows)
    const int wn = wid >> 2;       // 16-col stripe within 32-speaker chunk (0/1)
    const int l7 = lane & 7;

    // ---- prologue: A (128KB) + B0 (group 0), then B1 (group 1) ----
    {
        const __nv_bfloat16* As = g_Ebf + (size_t)bi * 128 * DD;
        #pragma unroll
        for (int it = 0; it < 32; it++) {
            const int u = tid + it * 256;
            const int r = u >> 6, cb = u & 63;
            cpa16(sb + SM_A + SWZ_OFF(r, cb), As + (size_t)r * DD + cb * 8);
        }
        const __nv_bfloat16* Bs = g_Cbf;
        #pragma unroll
        for (int it = 0; it < 8; it++) {
            const int u = tid + it * 256;
            const int r = u >> 6, cb = u & 63;
            cpa16(sb + SM_B(0) + SWZ_OFF(r, cb), Bs + (size_t)r * DD + cb * 8);
        }
        asm volatile("cp.async.commit_group;" ::: "memory");
        load_B_chunk(sb, 1, tid);
    }

    // per-thread ldmatrix addressing
    const uint32_t aoff0 = sb + SM_A + (uint32_t)(wm * 32 + (lane & 15)) * 1024;
    const uint32_t aoff1 = aoff0 + 16 * 1024;
    const int cbA = lane >> 4;              // A k-half select
    const int khB = (lane >> 3) & 1;        // B k-half select (x4 form)
    // B x4: lanes 0-7 -> (nt0,kh0), 8-15 -> (nt0,kh1), 16-23 -> (nt1,kh0), 24-31 -> (nt1,kh1)
    const uint32_t brow = (uint32_t)((wn * 16 + (lane >> 4) * 8 + l7) * 1024);

    // diagonal bookkeeping (warp-uniform speaker index)
    const int diag = bi * 4 + wm;
    const int dchunk = diag >> 5;           // 32-speaker chunk
    const int cc = diag & 31;               // col within chunk
    const int dwn = cc >> 4;                // 16-col stripe
    const int dj = cc & 15;                 // col within warp tile
    const int dnt = dj >> 3, down = (dj & 7) >> 1, de = dj & 1;

    // shift-free softmax state per row-set
    float os[4], od[4];
    #pragma unroll
    for (int i = 0; i < 4; i++) { os[i] = 0.f; od[i] = 0.f; }

    const float Wv = wp[0], Bv = bp[0];

    for (int c = 0; c < 16; c++) {
        if (c < 15) asm volatile("cp.async.wait_group 1;" ::: "memory");
        else        asm volatile("cp.async.wait_group 0;" ::: "memory");
        __syncthreads();

        const uint32_t Bbuf = sb + SM_B(c & 1);
        float acc[2][2][4];
        #pragma unroll
        for (int mt = 0; mt < 2; mt++)
            #pragma unroll
            for (int nt = 0; nt < 2; nt++)
                #pragma unroll
                for (int e = 0; e < 4; e++) acc[mt][nt][e] = 0.f;

        #pragma unroll 8
        for (int kk = 0; kk < 32; kk++) {
            const int cb = kk * 2;
            uint32_t a[2][4];
            ldsm_x4(a[0][0], a[0][1], a[0][2], a[0][3],
                    aoff0 + ((uint32_t)((cb + cbA) ^ l7) << 4));
            ldsm_x4(a[1][0], a[1][1], a[1][2], a[1][3],
                    aoff1 + ((uint32_t)((cb + cbA) ^ l7) << 4));
            uint32_t b[2][2];
            ldsm_x4(b[0][0], b[0][1], b[1][0], b[1][1],
                    Bbuf + brow + ((uint32_t)((cb + khB) ^ l7) << 4));
            #pragma unroll
            for (int mt = 0; mt < 2; mt++)
                #pragma unroll
                for (int nt = 0; nt < 2; nt++)
                    mma16816(acc[mt][nt][0], acc[mt][nt][1], acc[mt][nt][2], acc[mt][nt][3],
                             a[mt][0], a[mt][1], a[mt][2], a[mt][3], b[nt][0], b[nt][1]);
        }

        // ---- shift-free softmax accumulation (4 cols per row-set) ----
        const bool dhit = (c == dchunk) && (wn == dwn) && ((lane & 3) == down);
        #pragma unroll
        for (int mt = 0; mt < 2; mt++) {
            #pragma unroll
            for (int h = 0; h < 2; h++) {
                const int si = mt * 2 + h;
                float add = 0.f;
                #pragma unroll
                for (int nt = 0; nt < 2; nt++) {
                    const float v0 = fmaf(Wv, acc[mt][nt][h * 2 + 0], Bv);
                    const float v1 = fmaf(Wv, acc[mt][nt][h * 2 + 1], Bv);
                    add += __expf(v0) + __expf(v1);
                    if (dhit && nt == dnt) od[si] += (de ? v1 : v0);
                }
                os[si] += add;
            }
        }

        __syncthreads();
        if (c + 2 < 16) load_B_chunk(sb, c + 2, tid);
    }

    // ---- combine sums across the 4 lanes of each row quad ----
    #pragma unroll
    for (int si = 0; si < 4; si++) {
        #pragma unroll
        for (int off = 1; off <= 2; off <<= 1) {
            os[si] += __shfl_xor_sync(0xffffffffu, os[si], off);
            od[si] += __shfl_xor_sync(0xffffffffu, od[si], off);
        }
    }

    // ---- merge the two column-stripe warps (wid <-> wid+4) via smem ----
    float* sm_s = (float*)smem;            // [8][32]  (A region dead now)
    float* sm_d = sm_s + 256;              // [8][32]
    float* sm_r = sm_d + 256;              // partials
    __syncthreads();
    if ((lane & 3) == 0) {
        #pragma unroll
        for (int si = 0; si < 4; si++) {
            const int r = (si >> 1) * 16 + (si & 1) * 8 + (lane >> 2);
            sm_s[wid * 32 + r] = os[si];
            sm_d[wid * 32 + r] = od[si];
        }
    }
    __syncthreads();

    if (wid < 4) {   // warp wm merges its 32 rows from stripes wid and wid+4
        const float s = sm_s[wid * 32 + lane] + sm_s[(wid + 4) * 32 + lane];
        const float d = sm_d[wid * 32 + lane] + sm_d[(wid + 4) * 32 + lane];
        float local = d - __logf(s);
        #pragma unroll
        for (int o = 16; o > 0; o >>= 1)
            local += __shfl_xor_sync(0xffffffffu, local, o);
        if (lane == 0) sm_r[wid] = local;
    }
    __syncthreads();

    // ---- fused finalize: last block deterministically reduces g_part ----
    if (tid == 0) {
        g_part[bi] = sm_r[0] + sm_r[1] + sm_r[2] + sm_r[3];
        __threadfence();
        lastflag = (atomicAdd(&g_ctr, 1) == 127);
    }
    __syncthreads();
    if (lastflag) {
        float t = (tid < 128) ? g_part[tid] : 0.f;
        #pragma unroll
        for (int o = 16; o > 0; o >>= 1)
            t += __shfl_xor_sync(0xffffffffu, t, o);
        if (lane == 0) sm_r[8 + wid] = t;
        __syncthreads();
        if (tid == 0) {
            float tt = 0.f;
            #pragma unroll
            for (int i = 0; i < 8; i++) tt += sm_r[8 + i];
            out[0] = -tt * (1.0f / (float)NU);
            g_ctr = 0;   // reset for next graph replay
        }
    }
}

extern "C" void kernel_launch(void* const* d_in, const int* in_sizes, int n_in,
                              void* d_out, int out_size) {
    const float* emb = (const float*)d_in[0];
    const float* w = (const float*)d_in[1];
    const float* b = (const float*)d_in[2];
    float* out = (float*)d_out;

    cudaFuncSetAttribute(prep_kernel, cudaFuncAttributeMaxDynamicSharedMemorySize, 65536);
    cudaFuncSetAttribute(gemm_loss_kernel, cudaFuncAttributeMaxDynamicSharedMemorySize, SM_TOT);

    prep_kernel<<<NSPK, 256, 65536>>>(emb);
    gemm_loss_kernel<<<128, 256, SM_TOT>>>(w, b, out);
}

// round 14
// speedup vs baseline: 1.1906x; 1.0048x over previous
#include <cuda_runtime.h>
#include <cuda_bf16.h>
#include <cstdint>
#include <math.h>

#define NSPK 512
#define UU   32
#define DD   512
#define NU   (NSPK*UU)
#define EPS  1e-8f

// ---------------- device scratch (no cudaMalloc allowed) ----------------
__device__ __nv_bfloat16 g_Ebf[(size_t)NU * DD];   // normalized embeddings, bf16 (16 MB)
__device__ __nv_bfloat16 g_Cbf[NSPK * DD];         // normalized centroids, bf16 (0.5 MB)
__device__ float         g_part[128];              // per-GEMM-block partial sums
__device__ int           g_ctr;                    // zero-init completion counter

// ---------------- PTX helpers ----------------
static __device__ __forceinline__ uint32_t smem_u32(const void* p) {
    uint32_t a;
    asm("{ .reg .u64 t; cvta.to.shared.u64 t, %1; cvt.u32.u64 %0, t; }" : "=r"(a) : "l"(p));
    return a;
}
static __device__ __forceinline__ void ldsm_x4(uint32_t& r0, uint32_t& r1,
                                               uint32_t& r2, uint32_t& r3, uint32_t addr) {
    asm volatile("ldmatrix.sync.aligned.m8n8.x4.shared.b16 {%0,%1,%2,%3}, [%4];"
                 : "=r"(r0), "=r"(r1), "=r"(r2), "=r"(r3) : "r"(addr));
}
static __device__ __forceinline__ void mma16816(float& d0, float& d1, float& d2, float& d3,
                                                uint32_t a0, uint32_t a1, uint32_t a2, uint32_t a3,
                                                uint32_t b0, uint32_t b1) {
    asm volatile(
        "mma.sync.aligned.m16n8k16.row.col.f32.bf16.bf16.f32 "
        "{%0,%1,%2,%3}, {%4,%5,%6,%7}, {%8,%9}, {%0,%1,%2,%3};"
        : "+f"(d0), "+f"(d1), "+f"(d2), "+f"(d3)
        : "r"(a0), "r"(a1), "r"(a2), "r"(a3), "r"(b0), "r"(b1));
}
static __device__ __forceinline__ void cpa16(uint32_t dst, const void* gsrc) {
    unsigned long long g = (unsigned long long)__cvta_generic_to_global(gsrc);
    asm volatile("cp.async.cg.shared.global [%0], [%1], 16;" :: "r"(dst), "l"(g));
}

// ---------------------------------------------------------------------------
// Kernel P: per-speaker pass (centroid+norm fused, packed bf16 writes)
// grid = 512, 256 threads, 64KB dynamic smem
// ---------------------------------------------------------------------------
__global__ void __launch_bounds__(256, 1) prep_kernel(const float* __restrict__ emb) {
    extern __shared__ float s[];
    __shared__ float red[9];
    const int n = blockIdx.x, tid = threadIdx.x;
    const int w = tid >> 5, lane = tid & 31;

    const float4* src = reinterpret_cast<const float4*>(emb) + (size_t)n * 4096;
    float4* s4 = reinterpret_cast<float4*>(s);
    #pragma unroll
    for (int i = 0; i < 16; i++) s4[tid + i * 256] = src[tid + i * 256];
    __syncthreads();

    float c0 = 0.f, c1 = 0.f;
    #pragma unroll
    for (int u = 0; u < UU; u++) {
        c0 += s[u * DD + tid];
        c1 += s[u * DD + tid + 256];
    }
    c0 *= (1.0f / UU); c1 *= (1.0f / UU);
    float sq = fmaf(c0, c0, c1 * c1);
    #pragma unroll
    for (int o = 16; o > 0; o >>= 1) sq += __shfl_xor_sync(0xffffffffu, sq, o);
    if (lane == 0) red[w] = sq;
    __syncthreads();
    if (tid == 0) {
        float t = 0.f;
        #pragma unroll
        for (int i = 0; i < 8; i++) t += red[i];
        red[8] = 1.0f / fmaxf(sqrtf(t), EPS);
    }
    __syncthreads();
    const float invc = red[8];
    g_Cbf[n * DD + tid]       = __float2bfloat16(c0 * invc);
    g_Cbf[n * DD + tid + 256] = __float2bfloat16(c1 * invc);

    for (int u = w; u < UU; u += 8) {
        const float4* rowp = reinterpret_cast<const float4*>(s + u * DD);
        float4 v[4]; float ss = 0.f;
        #pragma unroll
        for (int j = 0; j < 4; j++) {
            v[j] = rowp[lane + j * 32];
            ss = fmaf(v[j].x, v[j].x, ss);
            ss = fmaf(v[j].y, v[j].y, ss);
            ss = fmaf(v[j].z, v[j].z, ss);
            ss = fmaf(v[j].w, v[j].w, ss);
        }
        #pragma unroll
        for (int o = 16; o > 0; o >>= 1) ss += __shfl_xor_sync(0xffffffffu, ss, o);
        const float inv = 1.0f / fmaxf(sqrtf(ss), EPS);
        uint2* dst = reinterpret_cast<uint2*>(g_Ebf + ((size_t)n * UU + u) * DD);
        #pragma unroll
        for (int j = 0; j < 4; j++) {
            __nv_bfloat162 lo = __floats2bfloat162_rn(v[j].x * inv, v[j].y * inv);
            __nv_bfloat162 hi = __floats2bfloat162_rn(v[j].z * inv, v[j].w * inv);
            uint2 pk;
            pk.x = *reinterpret_cast<uint32_t*>(&lo);
            pk.y = *reinterpret_cast<uint32_t*>(&hi);
            dst[lane + j * 32] = pk;
        }
    }
}

// ---------------------------------------------------------------------------
// Kernel G: HMMA GEMM, single wave, 3-stage B ring, fragment-pipelined.
// Block = 128 rows (A resident, 128KB); B = 16 chunks of 32 speakers in a
// 3-slot ring (3x32KB). grid = 128, 256 threads = 8 warps: 4(M) x 2(N),
// warp tile 32x16. Shift-free softmax, fused final reduction.
// ---------------------------------------------------------------------------
#define SM_A   0
#define SM_B(s) (131072 + (s) * 32768)
#define SM_TOT 229376
#define SWZ_OFF(r, cb) ((uint32_t)((r) * 1024 + ((((cb)) ^ ((r) & 7)) << 4)))

static __device__ __forceinline__ void load_B_chunk(uint32_t sb, int c, int tid) {
    const uint32_t buf = sb + SM_B(c % 3);
    const __nv_bfloat16* src = g_Cbf + (size_t)c * 32 * DD;
    #pragma unroll
    for (int it = 0; it < 8; it++) {
        const int u = tid + it * 256;
        const int r = u >> 6, cb = u & 63;
        cpa16(buf + SWZ_OFF(r, cb), src + (size_t)r * DD + cb * 8);
    }
    asm volatile("cp.async.commit_group;" ::: "memory");
}

__global__ void __launch_bounds__(256, 1)
gemm_loss_kernel(const float* __restrict__ wp, const float* __restrict__ bp,
                 float* __restrict__ out) {
    extern __shared__ char smem[];
    __shared__ int lastflag;
    const uint32_t sb = smem_u32(smem);
    const int tid = threadIdx.x, wid = tid >> 5, lane = tid & 31;
    const int bi = blockIdx.x;
    const int wm = wid & 3;        // row quarter (32 rows)
    const int wn = wid >> 2;       // 16-col stripe within 32-speaker chunk (0/1)
    const int l7 = lane & 7;

    // ---- prologue: A + B0 (group 0), then B1 (group 1) ----
    {
        const __nv_bfloat16* As = g_Ebf + (size_t)bi * 128 * DD;
        #pragma unroll
        for (int it = 0; it < 32; it++) {
            const int u = tid + it * 256;
            const int r = u >> 6, cb = u & 63;
            cpa16(sb + SM_A + SWZ_OFF(r, cb), As + (size_t)r * DD + cb * 8);
        }
        const __nv_bfloat16* Bs = g_Cbf;
        #pragma unroll
        for (int it = 0; it < 8; it++) {
            const int u = tid + it * 256;
            const int r = u >> 6, cb = u & 63;
            cpa16(sb + SM_B(0) + SWZ_OFF(r, cb), Bs + (size_t)r * DD + cb * 8);
        }
        asm volatile("cp.async.commit_group;" ::: "memory");
        load_B_chunk(sb, 1, tid);
    }

    // per-thread ldmatrix addressing
    const uint32_t aoff0 = sb + SM_A + (uint32_t)(wm * 32 + (lane & 15)) * 1024;
    const uint32_t aoff1 = aoff0 + 16 * 1024;
    const int cbA = lane >> 4;              // A k-half select
    const int khB = (lane >> 3) & 1;        // B k-half select (x4 form)
    const uint32_t brow = (uint32_t)((wn * 16 + (lane >> 4) * 8 + l7) * 1024);

    // diagonal bookkeeping (warp-uniform speaker index)
    const int diag = bi * 4 + wm;
    const int dchunk = diag >> 5;
    const int cc = diag & 31;
    const int dwn = cc >> 4;
    const int dj = cc & 15;
    const int dnt = dj >> 3, down = (dj & 7) >> 1, de = dj & 1;

    float os[4], od[4];
    #pragma unroll
    for (int i = 0; i < 4; i++) { os[i] = 0.f; od[i] = 0.f; }

    const float Wv = wp[0], Bv = bp[0];

    for (int c = 0; c < 16; c++) {
        if (c < 15) asm volatile("cp.async.wait_group 1;" ::: "memory");
        else        asm volatile("cp.async.wait_group 0;" ::: "memory");
        __syncthreads();   // chunk c ready; also releases slot (c+2)%3 (= chunk c-1's)
        if (c + 2 < 16) load_B_chunk(sb, c + 2, tid);

        const uint32_t Bbuf = sb + SM_B(c % 3);
        float acc[2][2][4];
        #pragma unroll
        for (int mt = 0; mt < 2; mt++)
            #pragma unroll
            for (int nt = 0; nt < 2; nt++)
                #pragma unroll
                for (int e = 0; e < 4; e++) acc[mt][nt][e] = 0.f;

        // ---- fragment-pipelined kk loop (ping/pong register buffers) ----
        uint32_t af[2][2][4], bf[2][2][2];
        {   // preload kk = 0
            const int cb = 0;
            ldsm_x4(af[0][0][0], af[0][0][1], af[0][0][2], af[0][0][3],
                    aoff0 + ((uint32_t)((cb + cbA) ^ l7) << 4));
            ldsm_x4(af[0][1][0], af[0][1][1], af[0][1][2], af[0][1][3],
                    aoff1 + ((uint32_t)((cb + cbA) ^ l7) << 4));
            ldsm_x4(bf[0][0][0], bf[0][0][1], bf[0][1][0], bf[0][1][1],
                    Bbuf + brow + ((uint32_t)((cb + khB) ^ l7) << 4));
        }
        #pragma unroll
        for (int kk = 0; kk < 32; kk++) {
            const int p = kk & 1, q = p ^ 1;
            if (kk < 31) {   // prefetch kk+1 into the other buffer
                const int cb = (kk + 1) * 2;
                ldsm_x4(af[q][0][0], af[q][0][1], af[q][0][2], af[q][0][3],
                        aoff0 + ((uint32_t)((cb + cbA) ^ l7) << 4));
                ldsm_x4(af[q][1][0], af[q][1][1], af[q][1][2], af[q][1][3],
                        aoff1 + ((uint32_t)((cb + cbA) ^ l7) << 4));
                ldsm_x4(bf[q][0][0], bf[q][0][1], bf[q][1][0], bf[q][1][1],
                        Bbuf + brow + ((uint32_t)((cb + khB) ^ l7) << 4));
            }
            #pragma unroll
            for (int mt = 0; mt < 2; mt++)
                #pragma unroll
                for (int nt = 0; nt < 2; nt++)
                    mma16816(acc[mt][nt][0], acc[mt][nt][1], acc[mt][nt][2], acc[mt][nt][3],
                             af[p][mt][0], af[p][mt][1], af[p][mt][2], af[p][mt][3],
                             bf[p][nt][0], bf[p][nt][1]);
        }

        // ---- shift-free softmax accumulation (4 cols per row-set) ----
        const bool dhit = (c == dchunk) && (wn == dwn) && ((lane & 3) == down);
        #pragma unroll
        for (int mt = 0; mt < 2; mt++) {
            #pragma unroll
            for (int h = 0; h < 2; h++) {
                const int si = mt * 2 + h;
                float add = 0.f;
                #pragma unroll
                for (int nt = 0; nt < 2; nt++) {
                    const float v0 = fmaf(Wv, acc[mt][nt][h * 2 + 0], Bv);
                    const float v1 = fmaf(Wv, acc[mt][nt][h * 2 + 1], Bv);
                    add += __expf(v0) + __expf(v1);
                    if (dhit && nt == dnt) od[si] += (de ? v1 : v0);
                }
                os[si] += add;
            }
        }
        // no trailing sync: next iteration's top sync protects slot reuse
    }

    // ---- combine sums across the 4 lanes of each row quad ----
    #pragma unroll
    for (int si = 0; si < 4; si++) {
        #pragma unroll
        for (int off = 1; off <= 2; off <<= 1) {
            os[si] += __shfl_xor_sync(0xffffffffu, os[si], off);
            od[si] += __shfl_xor_sync(0xffffffffu, od[si], off);
        }
    }

    // ---- merge the two column-stripe warps (wid <-> wid+4) via smem ----
    float* sm_s = (float*)smem;            // [8][32]  (A region dead now)
    float* sm_d = sm_s + 256;              // [8][32]
    float* sm_r = sm_d + 256;              // partials
    __syncthreads();
    if ((lane & 3) == 0) {
        #pragma unroll
        for (int si = 0; si < 4; si++) {
            const int r = (si >> 1) * 16 + (si & 1) * 8 + (lane >> 2);
            sm_s[wid * 32 + r] = os[si];
            sm_d[wid * 32 + r] = od[si];
        }
    }
    __syncthreads();

    if (wid < 4) {   // warp wm merges its 32 rows from stripes wid and wid+4
        const float s = sm_s[wid * 32 + lane] + sm_s[(wid + 4) * 32 + lane];
        const float d = sm_d[wid * 32 + lane] + sm_d[(wid + 4) * 32 + lane];
        float local = d - __logf(s);
        #pragma unroll
        for (int o = 16; o > 0; o >>= 1)
            local += __shfl_xor_sync(0xffffffffu, local, o);
        if (lane == 0) sm_r[wid] = local;
    }
    __syncthreads();

    // ---- fused finalize: last block deterministically reduces g_part ----
    if (tid == 0) {
        g_part[bi] = sm_r[0] + sm_r[1] + sm_r[2] + sm_r[3];
        __threadfence();
        lastflag = (atomicAdd(&g_ctr, 1) == 127);
    }
    __syncthreads();
    if (lastflag) {
        float t = (tid < 128) ? g_part[tid] : 0.f;
        #pragma unroll
        for (int o = 16; o > 0; o >>= 1)
            t += __shfl_xor_sync(0xffffffffu, t, o);
        if (lane == 0) sm_r[8 + wid] = t;
        __syncthreads();
        if (tid == 0) {
            float tt = 0.f;
            #pragma unroll
            for (int i = 0; i < 8; i++) tt += sm_r[8 + i];
            out[0] = -tt * (1.0f / (float)NU);
            g_ctr = 0;   // reset for next graph replay
        }
    }
}

extern "C" void kernel_launch(void* const* d_in, const int* in_sizes, int n_in,
                              void* d_out, int out_size) {
    const float* emb = (const float*)d_in[0];
    const float* w = (const float*)d_in[1];
    const float* b = (const float*)d_in[2];
    float* out = (float*)d_out;

    cudaFuncSetAttribute(prep_kernel, cudaFuncAttributeMaxDynamicSharedMemorySize, 65536);
    cudaFuncSetAttribute(gemm_loss_kernel, cudaFuncAttributeMaxDynamicSharedMemorySize, SM_TOT);

    prep_kernel<<<NSPK, 256, 65536>>>(emb);
    gemm_loss_kernel<<<128, 256, SM_TOT>>>(w, b, out);
}